// round 1
// baseline (speedup 1.0000x reference)
#include <cuda_runtime.h>
#include <cuda_bf16.h>
#include <math.h>

// Problem constants
#define BB   4
#define CC   1024
#define DD   1024
#define HH   16
#define DHH  64
#define CD   (CC*DD)          // 1048576
#define BCD  (BB*CD)          // 4194304
#define EXPF_ 4

// ---------------- scratch (static __device__ arrays; no runtime alloc) ---------------
__device__ float g_lnq[BCD];
__device__ float g_lnk[BCD];
__device__ float g_lnv[BCD];
__device__ float g_qlin[BCD];
__device__ float g_klin[BCD];
__device__ float g_vlin[BCD];
__device__ float g_x[BCD];        // x1 + attention_out (residual)
__device__ float g_xl[BCD];       // ffn layernorm out
__device__ float g_h1[BB*4096*1024]; // 16M floats

// =====================================================================================
// LayerNorm over the CHANNEL axis (axis=1 of (B,C,D)): for each (b,d) column of C
// elements (stride D in memory). Writes up to 3 affine outputs in one pass.
// grid: (D/32, B), block: 256 = 32 d-lanes x 8 c-lanes
// =====================================================================================
__global__ void ln3_kernel(const float* __restrict__ x,
    const float* __restrict__ w0, const float* __restrict__ b0, float* __restrict__ o0,
    const float* __restrict__ w1, const float* __restrict__ b1, float* __restrict__ o1,
    const float* __restrict__ w2, const float* __restrict__ b2, float* __restrict__ o2)
{
    const int dx   = threadIdx.x & 31;
    const int lane = threadIdx.x >> 5;       // 0..7
    const int d    = blockIdx.x * 32 + dx;
    const long base = (long)blockIdx.y * CD + d;

    float s = 0.f, ss = 0.f;
    for (int c = lane; c < CC; c += 8) {
        float v = x[base + (long)c * DD];
        s += v; ss += v * v;
    }
    __shared__ float sS[8][33], sQ[8][33];
    sS[lane][dx] = s; sQ[lane][dx] = ss;
    __syncthreads();
    if (lane == 0) {
        float ts = 0.f, tq = 0.f;
        #pragma unroll
        for (int i = 0; i < 8; i++) { ts += sS[i][dx]; tq += sQ[i][dx]; }
        float mean = ts * (1.0f / CC);
        float var  = tq * (1.0f / CC) - mean * mean;
        sS[0][dx] = mean;
        sQ[0][dx] = rsqrtf(var + 1e-6f);
    }
    __syncthreads();
    const float mean = sS[0][dx];
    const float rstd = sQ[0][dx];
    for (int c = lane; c < CC; c += 8) {
        long idx = base + (long)c * DD;
        float xn = (x[idx] - mean) * rstd;
        o0[idx] = w0[c] * xn + b0[c];
        if (o1) o1[idx] = w1[c] * xn + b1[c];
        if (o2) o2[idx] = w2[c] * xn + b2[c];
    }
}

// =====================================================================================
// softmax-one over rows of 1024: p = e / (1 + sum(e)), e = exp(x - max).  In-place.
// grid: one block per row (65536 rows), 256 threads, float4 per thread.
// =====================================================================================
__global__ void softmax_one_kernel(float* __restrict__ attn)
{
    float4* p = reinterpret_cast<float4*>(attn + (long)blockIdx.x * 1024);
    float4 f = p[threadIdx.x];

    float m = fmaxf(fmaxf(f.x, f.y), fmaxf(f.z, f.w));
    #pragma unroll
    for (int o = 16; o; o >>= 1) m = fmaxf(m, __shfl_xor_sync(0xffffffffu, m, o));
    __shared__ float smax[8], ssum[8];
    const int w = threadIdx.x >> 5, l = threadIdx.x & 31;
    if (l == 0) smax[w] = m;
    __syncthreads();
    if (threadIdx.x == 0) {
        float t = smax[0];
        #pragma unroll
        for (int i = 1; i < 8; i++) t = fmaxf(t, smax[i]);
        smax[0] = t;
    }
    __syncthreads();
    m = smax[0];

    float4 e;
    e.x = expf(f.x - m); e.y = expf(f.y - m);
    e.z = expf(f.z - m); e.w = expf(f.w - m);
    float s = e.x + e.y + e.z + e.w;
    #pragma unroll
    for (int o = 16; o; o >>= 1) s += __shfl_xor_sync(0xffffffffu, s, o);
    if (l == 0) ssum[w] = s;
    __syncthreads();
    if (threadIdx.x == 0) {
        float t = 0.f;
        #pragma unroll
        for (int i = 0; i < 8; i++) t += ssum[i];
        ssum[0] = t;
    }
    __syncthreads();
    const float inv = 1.0f / (1.0f + ssum[0]);
    e.x *= inv; e.y *= inv; e.z *= inv; e.w *= inv;
    p[threadIdx.x] = e;
}

// =====================================================================================
// Generic batched SGEMM:  C = alpha * A x op(B)  (+bias_m | +bias_n) (GELU) (+Add)
// A: (M,K) row-major, op(B)= B (K,N) if !TRANSB, B^T with B (N,K) if TRANSB.
// Per batch z: A += z*strideA, B += z*strideB,
//             C/Add offset = (z/cDiv)*cHi + (z%cDiv)*cLo  (handles attention scatter)
// Tile: 128x128x8, 256 threads, 8x8 per thread.
// =====================================================================================
template<bool TRANSB, bool BIAS_M, bool BIAS_N, bool GELU, bool ADD, bool SCALE>
__global__ void __launch_bounds__(256)
gemm_kernel(const float* __restrict__ A, long strideA, int lda,
            const float* __restrict__ B, long strideB, int ldb,
            float* __restrict__ C, int cDiv, long cHi, long cLo, int ldc,
            const float* __restrict__ Add,
            const float* __restrict__ bias,
            float alpha, int M, int N, int K)
{
    const int bz = blockIdx.z;
    A += (long)bz * strideA;
    B += (long)bz * strideB;
    const long coff = (long)(bz / cDiv) * cHi + (long)(bz % cDiv) * cLo;
    C += coff;
    const float* Addp = ADD ? (Add + coff) : nullptr;

    __shared__ float As[8][132];
    __shared__ float Bs[8][132];

    const int tid = threadIdx.x;
    const int tx = tid & 15, ty = tid >> 4;
    const int row0 = blockIdx.y * 128;
    const int col0 = blockIdx.x * 128;

    float acc[8][8];
    #pragma unroll
    for (int i = 0; i < 8; i++)
        #pragma unroll
        for (int j = 0; j < 8; j++) acc[i][j] = 0.f;

    for (int k0 = 0; k0 < K; k0 += 8) {
        // ---- load A tile (128 x 8) ----
        #pragma unroll
        for (int i = 0; i < 4; i++) {
            int idx = tid + i * 256;
            int m = idx >> 3, k = idx & 7;
            int gm = row0 + m;
            float v = (gm < M) ? A[(long)gm * lda + (k0 + k)] : 0.f;
            As[k][m] = v;
        }
        // ---- load B tile ----
        if (TRANSB) {
            #pragma unroll
            for (int i = 0; i < 4; i++) {
                int idx = tid + i * 256;
                int n = idx >> 3, k = idx & 7;
                int gn = col0 + n;
                float v = (gn < N) ? B[(long)gn * ldb + (k0 + k)] : 0.f;
                Bs[k][n] = v;
            }
        } else {
            #pragma unroll
            for (int i = 0; i < 4; i++) {
                int idx = tid + i * 256;
                int n = idx & 127, k = idx >> 7;
                int gn = col0 + n;
                float v = (gn < N) ? B[(long)(k0 + k) * ldb + gn] : 0.f;
                Bs[k][n] = v;
            }
        }
        __syncthreads();

        #pragma unroll
        for (int kk = 0; kk < 8; kk++) {
            float a[8], b[8];
            float4 a0 = *reinterpret_cast<const float4*>(&As[kk][ty * 8]);
            float4 a1 = *reinterpret_cast<const float4*>(&As[kk][ty * 8 + 4]);
            float4 b0 = *reinterpret_cast<const float4*>(&Bs[kk][tx * 8]);
            float4 b1 = *reinterpret_cast<const float4*>(&Bs[kk][tx * 8 + 4]);
            a[0]=a0.x; a[1]=a0.y; a[2]=a0.z; a[3]=a0.w;
            a[4]=a1.x; a[5]=a1.y; a[6]=a1.z; a[7]=a1.w;
            b[0]=b0.x; b[1]=b0.y; b[2]=b0.z; b[3]=b0.w;
            b[4]=b1.x; b[5]=b1.y; b[6]=b1.z; b[7]=b1.w;
            #pragma unroll
            for (int i = 0; i < 8; i++)
                #pragma unroll
                for (int j = 0; j < 8; j++)
                    acc[i][j] = fmaf(a[i], b[j], acc[i][j]);
        }
        __syncthreads();
    }

    // ---- epilogue ----
    #pragma unroll
    for (int i = 0; i < 8; i++) {
        int m = row0 + ty * 8 + i;
        if (m >= M) continue;
        #pragma unroll
        for (int j = 0; j < 8; j++) {
            int n = col0 + tx * 8 + j;
            if (n >= N) continue;
            float v = acc[i][j];
            if (SCALE)  v *= alpha;
            if (BIAS_M) v += bias[m];
            if (BIAS_N) v += bias[n];
            if (GELU)   v = 0.5f * v * (1.0f + erff(v * 0.70710678118654752f));
            if (ADD)    v += Addp[(long)m * ldc + n];
            C[(long)m * ldc + n] = v;
        }
    }
}

// =====================================================================================
extern "C" void kernel_launch(void* const* d_in, const int* in_sizes, int n_in,
                              void* d_out, int out_size)
{
    const float* x1      = (const float*)d_in[0];
    const float* lnq_w   = (const float*)d_in[1];
    const float* lnq_b   = (const float*)d_in[2];
    const float* lnk_w   = (const float*)d_in[3];
    const float* lnk_b   = (const float*)d_in[4];
    const float* lnv_w   = (const float*)d_in[5];
    const float* lnv_b   = (const float*)d_in[6];
    const float* wq      = (const float*)d_in[7];
    const float* bq      = (const float*)d_in[8];
    const float* wk      = (const float*)d_in[9];
    const float* bk      = (const float*)d_in[10];
    const float* wv      = (const float*)d_in[11];
    const float* bv      = (const float*)d_in[12];
    const float* ffnln_w = (const float*)d_in[13];
    const float* ffnln_b = (const float*)d_in[14];
    const float* conv1_w = (const float*)d_in[15];
    const float* conv1_b = (const float*)d_in[16];
    const float* conv2_w = (const float*)d_in[17];
    const float* conv2_b = (const float*)d_in[18];

    float *lnq, *lnk, *lnv, *qlin, *klin, *vlin, *xb, *xl, *h1;
    cudaGetSymbolAddress((void**)&lnq,  g_lnq);
    cudaGetSymbolAddress((void**)&lnk,  g_lnk);
    cudaGetSymbolAddress((void**)&lnv,  g_lnv);
    cudaGetSymbolAddress((void**)&qlin, g_qlin);
    cudaGetSymbolAddress((void**)&klin, g_klin);
    cudaGetSymbolAddress((void**)&vlin, g_vlin);
    cudaGetSymbolAddress((void**)&xb,   g_x);
    cudaGetSymbolAddress((void**)&xl,   g_xl);
    cudaGetSymbolAddress((void**)&h1,   g_h1);

    float* outx = (float*)d_out;            // (B,C,D) = 4M floats
    float* attn = outx + (long)BCD;         // (B,H,1024,1024) = 64M floats

    // 1) QKV LayerNorms (channel axis), one fused pass
    dim3 lng(DD / 32, BB);
    ln3_kernel<<<lng, 256>>>(x1, lnq_w, lnq_b, lnq, lnk_w, lnk_b, lnk,
                             lnv_w, lnv_b, lnv);

    // 2) QKV linears:  y = ln @ W^T + b   (M=4096, N=1024, K=1024)
    dim3 gqkv(8, 32, 1);
    gemm_kernel<true, false, true, false, false, false><<<gqkv, 256>>>(
        lnq, 0, 1024, wq, 0, 1024, qlin, 1, 0, 0, 1024, nullptr, bq, 1.f, 4096, 1024, 1024);
    gemm_kernel<true, false, true, false, false, false><<<gqkv, 256>>>(
        lnk, 0, 1024, wk, 0, 1024, klin, 1, 0, 0, 1024, nullptr, bk, 1.f, 4096, 1024, 1024);
    gemm_kernel<true, false, true, false, false, false><<<gqkv, 256>>>(
        lnv, 0, 1024, wv, 0, 1024, vlin, 1, 0, 0, 1024, nullptr, bv, 1.f, 4096, 1024, 1024);

    // 3) Attention logits S = 0.125 * Q K^T per (b,h); Q/K are contiguous (1024,64) blocks
    dim3 gqk(8, 8, BB * HH);
    gemm_kernel<true, false, false, false, false, true><<<gqk, 256>>>(
        qlin, 65536, 64, klin, 65536, 64, attn, 1, 1048576, 0, 1024,
        nullptr, nullptr, 0.125f, 1024, 1024, 64);

    // 4) softmax-one in place (writes final attn_weights output)
    softmax_one_kernel<<<BB * HH * 1024, 256>>>(attn);

    // 5) O = P V, scattered to x[b, i, h*64+e], fused residual add of x1 -> g_x
    dim3 gpv(1, 8, BB * HH);
    gemm_kernel<false, false, false, false, true, false><<<gpv, 256>>>(
        attn, 1048576, 1024, vlin, 65536, 64, xb, 16, 1048576, 64, 1024,
        x1, nullptr, 1.f, 1024, 64, 1024);

    // 6) FFN LayerNorm on x
    ln3_kernel<<<lng, 256>>>(xb, ffnln_w, ffnln_b, xl,
                             nullptr, nullptr, nullptr, nullptr, nullptr, nullptr);

    // 7) conv1: h1 = GELU(W1 @ xl + b1)   (M=4096, N=1024, K=1024, batch=B)
    dim3 gc1(8, 32, BB);
    gemm_kernel<false, true, false, true, false, false><<<gc1, 256>>>(
        conv1_w, 0, 1024, xl, (long)CD, 1024, h1, 1, (long)4096 * 1024, 0, 1024,
        nullptr, conv1_b, 1.f, 4096, 1024, 1024);

    // 8) conv2 + residual: out = x + (W2 @ h1 + b2)   (M=1024, N=1024, K=4096, batch=B)
    dim3 gc2(8, 8, BB);
    gemm_kernel<false, true, false, false, true, false><<<gc2, 256>>>(
        conv2_w, 0, 4096, h1, (long)4096 * 1024, 1024, outx, 1, (long)CD, 0, 1024,
        xb, conv2_b, 1.f, 1024, 1024, 4096);
}

// round 4
// speedup vs baseline: 1.5548x; 1.5548x over previous
#include <cuda_runtime.h>
#include <cuda_bf16.h>
#include <math.h>
#include <stdint.h>

// Problem constants
#define BB   4
#define CC   1024
#define DD   1024
#define HH   16
#define CD   (CC*DD)          // 1048576
#define BCD  (BB*CD)          // 4194304

// ---------------- scratch (static __device__ arrays; no runtime alloc) ---------------
__device__ float g_lnq[BCD];
__device__ float g_lnk[BCD];
__device__ float g_lnv[BCD];
__device__ float g_qlin[BCD];
__device__ float g_klin[BCD];
__device__ float g_vlin[BCD];
__device__ float g_x[BCD];        // x1 + attention_out (residual)
__device__ float g_xl[BCD];       // ffn layernorm out
__device__ float g_h1[BB*4096*1024]; // 16M floats

// =====================================================================================
// helpers
// =====================================================================================
__device__ __forceinline__ uint32_t smem_u32(const void* p) {
    uint32_t a;
    asm("{ .reg .u64 t; cvta.to.shared.u64 t, %1; cvt.u32.u64 %0, t; }" : "=r"(a) : "l"(p));
    return a;
}

__device__ __forceinline__ void ldsm4(uint32_t addr, uint32_t& r0, uint32_t& r1,
                                      uint32_t& r2, uint32_t& r3) {
    asm volatile("ldmatrix.sync.aligned.m8n8.x4.shared.b16 {%0,%1,%2,%3}, [%4];"
                 : "=r"(r0), "=r"(r1), "=r"(r2), "=r"(r3) : "r"(addr));
}

__device__ __forceinline__ void mma16816(float* c, const uint32_t* a, const uint32_t* b) {
    asm volatile(
        "mma.sync.aligned.m16n8k16.row.col.f32.bf16.bf16.f32 "
        "{%0,%1,%2,%3}, {%4,%5,%6,%7}, {%8,%9}, {%0,%1,%2,%3};"
        : "+f"(c[0]), "+f"(c[1]), "+f"(c[2]), "+f"(c[3])
        : "r"(a[0]), "r"(a[1]), "r"(a[2]), "r"(a[3]), "r"(b[0]), "r"(b[1]));
}

// split fp32 -> bf16 hi + bf16 lo (residual)
__device__ __forceinline__ void split1(float v, __nv_bfloat16& h, __nv_bfloat16& l) {
    h = __float2bfloat16(v);
    l = __float2bfloat16(v - __bfloat162float(h));
}

// =====================================================================================
// Tensor-core GEMM via mma.sync (bf16 hi/lo split, fp32-accurate):
//   C = alpha * A x Bs^T (+bias_m|+bias_n) (GELU) (+Add)
//   A: (M,K) K-contiguous, lda; per z: A += z*strideA
//   B: if BT, (N,K) K-contiguous; else (K,N) N-contiguous (transposed on smem store).
//      per z: B += (z/bDiv)*bHi + (z%bDiv)*bLo
//   C/Add per z offset: (z/cDiv)*cHi + (z%cDiv)*cLo
//   Block tile 128 x BN x 32, 256 threads, double-buffered smem.
// =====================================================================================
template<int BN, bool BT, bool BIAS_M, bool BIAS_N, bool GELUF, bool ADDF, bool SCALEF>
__global__ void __launch_bounds__(256, 1)
mma_gemm(const float* __restrict__ A, long strideA, int lda,
         const float* __restrict__ B, int bDiv, long bHi, long bLo, int ldb,
         float* __restrict__ C, int cDiv, long cHi, long cLo, int ldc,
         const float* __restrict__ Add, const float* __restrict__ bias,
         float alpha, int M, int N, int K)
{
    constexpr int BK = 32;
    constexpr int SK = 40;                         // padded smem K-stride (bf16 elems)
    constexpr int NW_M = (BN == 128) ? 2 : 4;
    constexpr int NW_N = 8 / NW_M;
    constexpr int WTM = 128 / NW_M;                // 64 or 32
    constexpr int WTN = BN / NW_N;                 // 32
    constexpr int MF = WTM / 16;                   // 4 or 2
    constexpr int NF = WTN / 8;                    // 4
    constexpr int ASZ = 128 * SK;                  // bf16 elems per A matrix
    constexpr int BSZ = BN * SK;
    constexpr int STAGE = 2 * ASZ + 2 * BSZ;       // hi+lo for A and B
    constexpr int NA4 = 128 * BK / 4 / 256;        // 4 float4 per thread (A)
    constexpr int NB4 = BN * BK / 4 / 256;         // 4 or 2 (B)

    extern __shared__ __nv_bfloat16 sm[];

    const int tid = threadIdx.x, wid = tid >> 5, lid = tid & 31;
    const int wm = wid / NW_N, wn = wid % NW_N;
    const int z = blockIdx.z;
    const int row0 = blockIdx.y * 128, col0 = blockIdx.x * BN;
    A += (long)z * strideA;
    B += (long)(z / bDiv) * bHi + (long)(z % bDiv) * bLo;
    const long coff = (long)(z / cDiv) * cHi + (long)(z % cDiv) * cLo;

    float acc[MF][NF][4];
#pragma unroll
    for (int i = 0; i < MF; i++)
#pragma unroll
        for (int j = 0; j < NF; j++)
#pragma unroll
            for (int r = 0; r < 4; r++) acc[i][j][r] = 0.f;

    const int nIt = K / BK;
    float4 av[NA4], bv[NB4];

    // ---- tile load (global -> regs) ----
    auto loadTile = [&](int it) {
        const int k0 = it * BK;
#pragma unroll
        for (int i = 0; i < NA4; i++) {
            int idx = tid + (i << 8);
            int r = idx >> 3, c4 = idx & 7;
            av[i] = *(const float4*)(A + (long)(row0 + r) * lda + k0 + (c4 << 2));
        }
        if (BT) {
#pragma unroll
            for (int i = 0; i < NB4; i++) {
                int idx = tid + (i << 8);
                int r = idx >> 3, c4 = idx & 7;
                bv[i] = *(const float4*)(B + (long)(col0 + r) * ldb + k0 + (c4 << 2));
            }
        } else {
#pragma unroll
            for (int i = 0; i < NB4; i++) {
                int idx = tid + (i << 8);
                int k = idx / (BN / 4), n4 = idx % (BN / 4);
                bv[i] = *(const float4*)(B + (long)(k0 + k) * ldb + col0 + (n4 << 2));
            }
        }
    };

    // ---- tile store (regs -> smem hi/lo, padded layout) ----
    auto storeTile = [&](int s) {
        __nv_bfloat16* sAhi = sm + s * STAGE;
        __nv_bfloat16* sAlo = sAhi + ASZ;
        __nv_bfloat16* sBhi = sAlo + ASZ;
        __nv_bfloat16* sBlo = sBhi + BSZ;
#pragma unroll
        for (int i = 0; i < NA4; i++) {
            int idx = tid + (i << 8);
            int r = idx >> 3, c4 = idx & 7;
            __nv_bfloat16 h[4], l[4];
            split1(av[i].x, h[0], l[0]); split1(av[i].y, h[1], l[1]);
            split1(av[i].z, h[2], l[2]); split1(av[i].w, h[3], l[3]);
            *(uint2*)(sAhi + r * SK + c4 * 4) = *(uint2*)h;
            *(uint2*)(sAlo + r * SK + c4 * 4) = *(uint2*)l;
        }
        if (BT) {
#pragma unroll
            for (int i = 0; i < NB4; i++) {
                int idx = tid + (i << 8);
                int r = idx >> 3, c4 = idx & 7;
                __nv_bfloat16 h[4], l[4];
                split1(bv[i].x, h[0], l[0]); split1(bv[i].y, h[1], l[1]);
                split1(bv[i].z, h[2], l[2]); split1(bv[i].w, h[3], l[3]);
                *(uint2*)(sBhi + r * SK + c4 * 4) = *(uint2*)h;
                *(uint2*)(sBlo + r * SK + c4 * 4) = *(uint2*)l;
            }
        } else {
#pragma unroll
            for (int i = 0; i < NB4; i++) {
                int idx = tid + (i << 8);
                int k = idx / (BN / 4), n0 = (idx % (BN / 4)) << 2;
                float vv[4] = {bv[i].x, bv[i].y, bv[i].z, bv[i].w};
#pragma unroll
                for (int j = 0; j < 4; j++) {
                    __nv_bfloat16 h, l;
                    split1(vv[j], h, l);
                    sBhi[(n0 + j) * SK + k] = h;
                    sBlo[(n0 + j) * SK + k] = l;
                }
            }
        }
    };

    loadTile(0);
    storeTile(0);

    for (int it = 0; it < nIt; it++) {
        __syncthreads();
        if (it + 1 < nIt) loadTile(it + 1);

        const int s = it & 1;
        const uint32_t sAhiB = smem_u32(sm + s * STAGE);
        const uint32_t sAloB = sAhiB + ASZ * 2;
        const uint32_t sBhiB = sAloB + ASZ * 2;
        const uint32_t sBloB = sBhiB + BSZ * 2;

        // lane-pattern offsets (bytes)
        const uint32_t aLane = (uint32_t)((wm * WTM + (lid & 15)) * SK + (lid >> 4) * 8) * 2;
        const uint32_t bLane = (uint32_t)((wn * WTN + (lid & 7) + (lid >> 4) * 8) * SK
                                          + ((lid >> 3) & 1) * 8) * 2;

#pragma unroll
        for (int ks = 0; ks < 2; ks++) {
            const uint32_t kOff = (uint32_t)(ks * 16) * 2;
            uint32_t ah[MF][4], al[MF][4], bh[NF][2], bl[NF][2];
#pragma unroll
            for (int mf = 0; mf < MF; mf++) {
                uint32_t off = aLane + (uint32_t)(mf * 16 * SK) * 2 + kOff;
                ldsm4(sAhiB + off, ah[mf][0], ah[mf][1], ah[mf][2], ah[mf][3]);
                ldsm4(sAloB + off, al[mf][0], al[mf][1], al[mf][2], al[mf][3]);
            }
#pragma unroll
            for (int p = 0; p < NF / 2; p++) {
                uint32_t off = bLane + (uint32_t)(p * 16 * SK) * 2 + kOff;
                ldsm4(sBhiB + off, bh[2*p][0], bh[2*p][1], bh[2*p+1][0], bh[2*p+1][1]);
                ldsm4(sBloB + off, bl[2*p][0], bl[2*p][1], bl[2*p+1][0], bl[2*p+1][1]);
            }
#pragma unroll
            for (int mf = 0; mf < MF; mf++)
#pragma unroll
                for (int nf = 0; nf < NF; nf++) {
                    mma16816(acc[mf][nf], ah[mf], bh[nf]);
                    mma16816(acc[mf][nf], ah[mf], bl[nf]);
                    mma16816(acc[mf][nf], al[mf], bh[nf]);
                }
        }
        if (it + 1 < nIt) storeTile((it + 1) & 1);
    }

    // ---- epilogue: fragments -> global with fused ops ----
    float* Cp = C + coff;
    const float* Ap2 = ADDF ? (Add + coff) : nullptr;
    const int rBase = row0 + wm * WTM + (lid >> 2);
    const int cBase = col0 + wn * WTN + (lid & 3) * 2;
#pragma unroll
    for (int mf = 0; mf < MF; mf++) {
#pragma unroll
        for (int half = 0; half < 2; half++) {
            const int gr = rBase + mf * 16 + half * 8;
            const float bm = BIAS_M ? bias[gr] : 0.f;
#pragma unroll
            for (int nf = 0; nf < NF; nf++) {
                const int gc = cBase + nf * 8;
                float v0 = acc[mf][nf][half * 2 + 0];
                float v1 = acc[mf][nf][half * 2 + 1];
                if (SCALEF) { v0 *= alpha; v1 *= alpha; }
                if (BIAS_M) { v0 += bm; v1 += bm; }
                if (BIAS_N) { v0 += bias[gc]; v1 += bias[gc + 1]; }
                if (GELUF) {
                    v0 = 0.5f * v0 * (1.0f + erff(v0 * 0.70710678118654752f));
                    v1 = 0.5f * v1 * (1.0f + erff(v1 * 0.70710678118654752f));
                }
                long off = (long)gr * ldc + gc;
                if (ADDF) { v0 += Ap2[off]; v1 += Ap2[off + 1]; }
                *(float2*)(Cp + off) = make_float2(v0, v1);
            }
        }
    }
}

// =====================================================================================
// LayerNorm over the CHANNEL axis; up to 3 affine outputs in one pass.
// =====================================================================================
__global__ void ln3_kernel(const float* __restrict__ x,
    const float* __restrict__ w0, const float* __restrict__ b0, float* __restrict__ o0,
    const float* __restrict__ w1, const float* __restrict__ b1, float* __restrict__ o1,
    const float* __restrict__ w2, const float* __restrict__ b2, float* __restrict__ o2)
{
    const int dx   = threadIdx.x & 31;
    const int lane = threadIdx.x >> 5;
    const int d    = blockIdx.x * 32 + dx;
    const long base = (long)blockIdx.y * CD + d;

    float s = 0.f, ss = 0.f;
    for (int c = lane; c < CC; c += 8) {
        float v = x[base + (long)c * DD];
        s += v; ss += v * v;
    }
    __shared__ float sS[8][33], sQ[8][33];
    sS[lane][dx] = s; sQ[lane][dx] = ss;
    __syncthreads();
    if (lane == 0) {
        float ts = 0.f, tq = 0.f;
        #pragma unroll
        for (int i = 0; i < 8; i++) { ts += sS[i][dx]; tq += sQ[i][dx]; }
        float mean = ts * (1.0f / CC);
        float var  = tq * (1.0f / CC) - mean * mean;
        sS[0][dx] = mean;
        sQ[0][dx] = rsqrtf(var + 1e-6f);
    }
    __syncthreads();
    const float mean = sS[0][dx];
    const float rstd = sQ[0][dx];
    for (int c = lane; c < CC; c += 8) {
        long idx = base + (long)c * DD;
        float xn = (x[idx] - mean) * rstd;
        o0[idx] = w0[c] * xn + b0[c];
        if (o1) o1[idx] = w1[c] * xn + b1[c];
        if (o2) o2[idx] = w2[c] * xn + b2[c];
    }
}

// =====================================================================================
// softmax-one over rows of 1024: p = e / (1 + sum(e)), e = exp(x - max). In-place.
// =====================================================================================
__global__ void softmax_one_kernel(float* __restrict__ attn)
{
    float4* p = reinterpret_cast<float4*>(attn + (long)blockIdx.x * 1024);
    float4 f = p[threadIdx.x];

    float m = fmaxf(fmaxf(f.x, f.y), fmaxf(f.z, f.w));
    #pragma unroll
    for (int o = 16; o; o >>= 1) m = fmaxf(m, __shfl_xor_sync(0xffffffffu, m, o));
    __shared__ float smax[8], ssum[8];
    const int w = threadIdx.x >> 5, l = threadIdx.x & 31;
    if (l == 0) smax[w] = m;
    __syncthreads();
    if (threadIdx.x == 0) {
        float t = smax[0];
        #pragma unroll
        for (int i = 1; i < 8; i++) t = fmaxf(t, smax[i]);
        smax[0] = t;
    }
    __syncthreads();
    m = smax[0];

    float4 e;
    e.x = expf(f.x - m); e.y = expf(f.y - m);
    e.z = expf(f.z - m); e.w = expf(f.w - m);
    float s = e.x + e.y + e.z + e.w;
    #pragma unroll
    for (int o = 16; o; o >>= 1) s += __shfl_xor_sync(0xffffffffu, s, o);
    if (l == 0) ssum[w] = s;
    __syncthreads();
    if (threadIdx.x == 0) {
        float t = 0.f;
        #pragma unroll
        for (int i = 0; i < 8; i++) t += ssum[i];
        ssum[0] = t;
    }
    __syncthreads();
    const float inv = 1.0f / (1.0f + ssum[0]);
    e.x *= inv; e.y *= inv; e.z *= inv; e.w *= inv;
    p[threadIdx.x] = e;
}

// =====================================================================================
extern "C" void kernel_launch(void* const* d_in, const int* in_sizes, int n_in,
                              void* d_out, int out_size)
{
    const float* x1      = (const float*)d_in[0];
    const float* lnq_w   = (const float*)d_in[1];
    const float* lnq_b   = (const float*)d_in[2];
    const float* lnk_w   = (const float*)d_in[3];
    const float* lnk_b   = (const float*)d_in[4];
    const float* lnv_w   = (const float*)d_in[5];
    const float* lnv_b   = (const float*)d_in[6];
    const float* wq      = (const float*)d_in[7];
    const float* bq      = (const float*)d_in[8];
    const float* wk      = (const float*)d_in[9];
    const float* bk      = (const float*)d_in[10];
    const float* wv      = (const float*)d_in[11];
    const float* bv      = (const float*)d_in[12];
    const float* ffnln_w = (const float*)d_in[13];
    const float* ffnln_b = (const float*)d_in[14];
    const float* conv1_w = (const float*)d_in[15];
    const float* conv1_b = (const float*)d_in[16];
    const float* conv2_w = (const float*)d_in[17];
    const float* conv2_b = (const float*)d_in[18];

    float *lnq, *lnk, *lnv, *qlin, *klin, *vlin, *xb, *xl, *h1;
    cudaGetSymbolAddress((void**)&lnq,  g_lnq);
    cudaGetSymbolAddress((void**)&lnk,  g_lnk);
    cudaGetSymbolAddress((void**)&lnv,  g_lnv);
    cudaGetSymbolAddress((void**)&qlin, g_qlin);
    cudaGetSymbolAddress((void**)&klin, g_klin);
    cudaGetSymbolAddress((void**)&vlin, g_vlin);
    cudaGetSymbolAddress((void**)&xb,   g_x);
    cudaGetSymbolAddress((void**)&xl,   g_xl);
    cudaGetSymbolAddress((void**)&h1,   g_h1);

    float* outx = (float*)d_out;            // (B,C,D) = 4M floats
    float* attn = outx + (long)BCD;         // (B,H,1024,1024) = 64M floats

    // dynamic smem: 2 stages x (A hi/lo + B hi/lo), bf16 elems, SK=40 padding
    const int SM128 = 2 * (2 * 128 * 40 + 2 * 128 * 40) * 2;  // 81920 bytes
    const int SM64  = 2 * (2 * 128 * 40 + 2 * 64 * 40) * 2;   // 61440 bytes

    auto kQKV = mma_gemm<128, true,  false, true,  false, false, false>;
    auto kQK  = mma_gemm<128, true,  false, false, false, false, true >;
    auto kPV  = mma_gemm<64,  false, false, false, false, true,  false>;
    auto kC1  = mma_gemm<128, false, true,  false, true,  false, false>;
    auto kC2  = mma_gemm<128, false, true,  false, false, true,  false>;
    cudaFuncSetAttribute(kQKV, cudaFuncAttributeMaxDynamicSharedMemorySize, SM128);
    cudaFuncSetAttribute(kQK,  cudaFuncAttributeMaxDynamicSharedMemorySize, SM128);
    cudaFuncSetAttribute(kPV,  cudaFuncAttributeMaxDynamicSharedMemorySize, SM64);
    cudaFuncSetAttribute(kC1,  cudaFuncAttributeMaxDynamicSharedMemorySize, SM128);
    cudaFuncSetAttribute(kC2,  cudaFuncAttributeMaxDynamicSharedMemorySize, SM128);

    // 1) QKV LayerNorms (channel axis), one fused pass
    dim3 lng(DD / 32, BB);
    ln3_kernel<<<lng, 256>>>(x1, lnq_w, lnq_b, lnq, lnk_w, lnk_b, lnk,
                             lnv_w, lnv_b, lnv);

    // 2) QKV linears: y = ln @ W^T + b   (M=4096, N=1024, K=1024)
    dim3 gqkv(8, 32, 1);
    kQKV<<<gqkv, 256, SM128>>>(lnq, 0, 1024, wq, 1, 0, 0, 1024,
                               qlin, 1, 0, 0, 1024, nullptr, bq, 1.f, 4096, 1024, 1024);
    kQKV<<<gqkv, 256, SM128>>>(lnk, 0, 1024, wk, 1, 0, 0, 1024,
                               klin, 1, 0, 0, 1024, nullptr, bk, 1.f, 4096, 1024, 1024);
    kQKV<<<gqkv, 256, SM128>>>(lnv, 0, 1024, wv, 1, 0, 0, 1024,
                               vlin, 1, 0, 0, 1024, nullptr, bv, 1.f, 4096, 1024, 1024);

    // 3) S = 0.125 * Q K^T per (b,h); direct reshape -> head block z*65536, ld=64
    dim3 gqk(8, 8, BB * HH);
    kQK<<<gqk, 256, SM128>>>(qlin, 65536, 64, klin, 1, 65536, 0, 64,
                             attn, 1, 1048576, 0, 1024, nullptr, nullptr,
                             0.125f, 1024, 1024, 64);

    // 4) softmax-one in place (final attn_weights output)
    softmax_one_kernel<<<BB * HH * 1024, 256>>>(attn);

    // 5) O = P V: V is the contiguous head block vlin + z*65536, (K=1024, N=64) ld=64.
    //    Output scattered to x[b, i, h*64+e] (transpose), fused residual add of x1.
    dim3 gpv(1, 8, BB * HH);
    kPV<<<gpv, 256, SM64>>>(attn, 1048576, 1024, vlin, 1, 65536, 0, 64,
                            xb, 16, (long)CD, 64, 1024, x1, nullptr,
                            1.f, 1024, 64, 1024);

    // 6) FFN LayerNorm on x
    ln3_kernel<<<lng, 256>>>(xb, ffnln_w, ffnln_b, xl,
                             nullptr, nullptr, nullptr, nullptr, nullptr, nullptr);

    // 7) conv1: h1 = GELU(W1 @ xl + b1)   (M=4096, N=1024, K=1024, batch=B)
    dim3 gc1(8, 32, BB);
    kC1<<<gc1, 256, SM128>>>(conv1_w, 0, 1024, xl, 1, (long)CD, 0, 1024,
                             h1, 1, (long)4096 * 1024, 0, 1024, nullptr, conv1_b,
                             1.f, 4096, 1024, 1024);

    // 8) conv2 + residual: out = x + (W2 @ h1 + b2)   (M=1024, N=1024, K=4096)
    dim3 gc2(8, 8, BB);
    kC2<<<gc2, 256, SM128>>>(conv2_w, 0, 4096, h1, 1, (long)4096 * 1024, 0, 1024,
                             outx, 1, (long)CD, 0, 1024, xb, conv2_b,
                             1.f, 1024, 1024, 4096);
}

// round 5
// speedup vs baseline: 2.5752x; 1.6563x over previous
#include <cuda_runtime.h>
#include <cuda_bf16.h>
#include <math.h>
#include <stdint.h>

#define BB   4
#define CC   1024
#define DD   1024
#define HH   16
#define CD   (CC*DD)          // 1048576
#define BCD  (BB*CD)          // 4194304
#define H1SZ (BB*4096*1024)   // 16777216

// ---------------- scratch (static __device__ arrays; no runtime alloc) ---------------
__device__ __nv_bfloat16 g_ln_hi[3*BCD],  g_ln_lo[3*BCD];    // lnq/lnk/lnv planes
__device__ __nv_bfloat16 g_qkv_hi[3*BCD], g_qkv_lo[3*BCD];   // q/k/v planes
__device__ __nv_bfloat16 g_w_hi[3*CD],    g_w_lo[3*CD];      // wq/wk/wv planes
__device__ __nv_bfloat16 g_c1w_hi[4*CD],  g_c1w_lo[4*CD];
__device__ __nv_bfloat16 g_c2w_hi[4*CD],  g_c2w_lo[4*CD];
__device__ __nv_bfloat16 g_xl_hi[BCD],    g_xl_lo[BCD];
__device__ __nv_bfloat16 g_h1_hi[H1SZ],   g_h1_lo[H1SZ];
__device__ float g_x[BCD];          // x1 + attention out (residual)
__device__ float g_bqkv[3*1024];    // gathered q/k/v biases

// =====================================================================================
// helpers
// =====================================================================================
__device__ __forceinline__ uint32_t smem_u32(const void* p) {
    uint32_t a;
    asm("{ .reg .u64 t; cvta.to.shared.u64 t, %1; cvt.u32.u64 %0, t; }" : "=r"(a) : "l"(p));
    return a;
}
__device__ __forceinline__ void cpa16(uint32_t s, const void* g) {
    asm volatile("cp.async.cg.shared.global [%0], [%1], 16;" :: "r"(s), "l"(g));
}
__device__ __forceinline__ void ldsm4(uint32_t addr, uint32_t& r0, uint32_t& r1,
                                      uint32_t& r2, uint32_t& r3) {
    asm volatile("ldmatrix.sync.aligned.m8n8.x4.shared.b16 {%0,%1,%2,%3}, [%4];"
                 : "=r"(r0), "=r"(r1), "=r"(r2), "=r"(r3) : "r"(addr));
}
__device__ __forceinline__ void ldsm4t(uint32_t addr, uint32_t& r0, uint32_t& r1,
                                       uint32_t& r2, uint32_t& r3) {
    asm volatile("ldmatrix.sync.aligned.m8n8.x4.trans.shared.b16 {%0,%1,%2,%3}, [%4];"
                 : "=r"(r0), "=r"(r1), "=r"(r2), "=r"(r3) : "r"(addr));
}
__device__ __forceinline__ void mma16816(float* c, const uint32_t* a, const uint32_t* b) {
    asm volatile(
        "mma.sync.aligned.m16n8k16.row.col.f32.bf16.bf16.f32 "
        "{%0,%1,%2,%3}, {%4,%5,%6,%7}, {%8,%9}, {%0,%1,%2,%3};"
        : "+f"(c[0]), "+f"(c[1]), "+f"(c[2]), "+f"(c[3])
        : "r"(a[0]), "r"(a[1]), "r"(a[2]), "r"(a[3]), "r"(b[0]), "r"(b[1]));
}
__device__ __forceinline__ void split1(float v, __nv_bfloat16& h, __nv_bfloat16& l) {
    h = __float2bfloat16(v);
    l = __float2bfloat16(v - __bfloat162float(h));
}

// =====================================================================================
// Tensor-core GEMM (pre-split bf16 hi/lo operands, fp32-class accuracy via 3-MMA):
//   C = alpha * A x B^T (+bias) (GELU) (+Add), batched along blockIdx.z.
//   A: bf16 hi/lo planes (M,K) K-contig (or fp32 if ACONV; converted in-kernel).
//   B: bf16 hi/lo; BTRANS=0: (N,K) K-contig (ldsm non-trans);
//      BTRANS=1: (K,N) N-contig natural layout (ldsm .trans).
//   Block tile 128 x BN x 32, 256 threads, 3-stage cp.async pipeline.
// =====================================================================================
template<int BN, bool BTRANS, bool ACONV, bool BIAS_M, bool BIAS_N,
         bool GELUF, bool ADDF, bool SCALEF, bool OSPLIT>
__global__ void __launch_bounds__(256, 1)
tc2_gemm(const void* Ahv, const __nv_bfloat16* Alo, long strideA, int lda,
         const __nv_bfloat16* Bhi, const __nv_bfloat16* Blo,
         int bDiv, long bHi, long bLo, int ldb,
         float* Cf, __nv_bfloat16* Chi, __nv_bfloat16* Clo,
         int cDiv, long cHi, long cLo, int ldc,
         const float* Add, const float* bias, int biasZ,
         float alpha, int M, int N, int K)
{
    constexpr int BK  = 32;
    constexpr int SKA = 40;                        // A smem row stride (elems)
    constexpr int SN  = BN + 8;                    // trans-B smem row stride
    constexpr int ASZ = 128 * SKA;                 // elems per A plane
    constexpr int BSZ = BTRANS ? (BK * SN) : (BN * SKA);
    constexpr int STAGE = 2 * ASZ + 2 * BSZ;       // elems per stage
    constexpr int NW_M = (BN == 128) ? 2 : 4;
    constexpr int NW_N = 8 / NW_M;
    constexpr int WTM = 128 / NW_M;
    constexpr int WTN = BN / NW_N;
    constexpr int MF = WTM / 16;
    constexpr int NF = WTN / 8;

    extern __shared__ __nv_bfloat16 sm[];

    const int tid = threadIdx.x, wid = tid >> 5, lid = tid & 31;
    const int wm = wid / NW_N, wn = wid % NW_N;
    const int z = blockIdx.z;
    const int row0 = blockIdx.y * 128, col0 = blockIdx.x * BN;

    const __nv_bfloat16* Ahi = ACONV ? nullptr : ((const __nv_bfloat16*)Ahv + (long)z * strideA);
    const __nv_bfloat16* Alz = ACONV ? nullptr : (Alo + (long)z * strideA);
    const float* Af = ACONV ? ((const float*)Ahv + (long)z * strideA) : nullptr;
    Bhi += (long)(z / bDiv) * bHi + (long)(z % bDiv) * bLo;
    Blo += (long)(z / bDiv) * bHi + (long)(z % bDiv) * bLo;
    const long coff = (long)(z / cDiv) * cHi + (long)(z % cDiv) * cLo;
    if (BIAS_N || BIAS_M) bias += (long)z * biasZ;

    const uint32_t smBase = smem_u32(sm);
    const int nIt = K / BK;

    float acc[MF][NF][4];
#pragma unroll
    for (int i = 0; i < MF; i++)
#pragma unroll
        for (int j = 0; j < NF; j++)
#pragma unroll
            for (int r = 0; r < 4; r++) acc[i][j][r] = 0.f;

    float4 av[4];  // ACONV staging

    // ---- cp.async issue for one tile into stage st ----
    auto issueTile = [&](int it, int st) {
        const int k0 = it * BK;
        const uint32_t sbase = smBase + (uint32_t)(st * STAGE) * 2;
        if (!ACONV) {
#pragma unroll
            for (int pl = 0; pl < 2; pl++) {
                const __nv_bfloat16* Ag = pl ? Alz : Ahi;
                const uint32_t sd = sbase + (uint32_t)(pl * ASZ) * 2;
#pragma unroll
                for (int i = 0; i < 2; i++) {
                    int idx = tid + (i << 8);
                    int r = idx >> 2, c8 = (idx & 3) << 3;
                    cpa16(sd + (uint32_t)(r * SKA + c8) * 2,
                          Ag + (long)(row0 + r) * lda + k0 + c8);
                }
            }
        }
        if (BTRANS) {
            constexpr int CH = BK * BN / 8 / 256;  // chunks/thread/plane
#pragma unroll
            for (int pl = 0; pl < 2; pl++) {
                const __nv_bfloat16* Bg = pl ? Blo : Bhi;
                const uint32_t sd = sbase + (uint32_t)(2 * ASZ + pl * BSZ) * 2;
#pragma unroll
                for (int i = 0; i < CH; i++) {
                    int idx = tid + (i << 8);
                    int k = idx / (BN / 8), c8 = (idx % (BN / 8)) << 3;
                    cpa16(sd + (uint32_t)(k * SN + c8) * 2,
                          Bg + (long)(k0 + k) * ldb + col0 + c8);
                }
            }
        } else {
#pragma unroll
            for (int pl = 0; pl < 2; pl++) {
                const __nv_bfloat16* Bg = pl ? Blo : Bhi;
                const uint32_t sd = sbase + (uint32_t)(2 * ASZ + pl * BSZ) * 2;
#pragma unroll
                for (int i = 0; i < BN / 64; i++) {
                    int idx = tid + (i << 8);
                    int r = idx >> 2, c8 = (idx & 3) << 3;
                    cpa16(sd + (uint32_t)(r * SKA + c8) * 2,
                          Bg + (long)(col0 + r) * ldb + k0 + c8);
                }
            }
        }
    };
    auto ldgA = [&](int it) {
        const int k0 = it * BK;
#pragma unroll
        for (int i = 0; i < 4; i++) {
            int idx = tid + (i << 8);
            int r = idx >> 3, c4 = (idx & 7) << 2;
            av[i] = *(const float4*)(Af + (long)(row0 + r) * lda + k0 + c4);
        }
    };
    auto stsA = [&](int st) {
        __nv_bfloat16* sAhi = sm + st * STAGE;
        __nv_bfloat16* sAlo = sAhi + ASZ;
#pragma unroll
        for (int i = 0; i < 4; i++) {
            int idx = tid + (i << 8);
            int r = idx >> 3, c4 = (idx & 7) << 2;
            __nv_bfloat16 h[4], l[4];
            split1(av[i].x, h[0], l[0]); split1(av[i].y, h[1], l[1]);
            split1(av[i].z, h[2], l[2]); split1(av[i].w, h[3], l[3]);
            *(uint2*)(sAhi + r * SKA + c4) = *(uint2*)h;
            *(uint2*)(sAlo + r * SKA + c4) = *(uint2*)l;
        }
    };

    // ---- prologue ----
    if (ACONV) { ldgA(0); stsA(0); }
    issueTile(0, 0);
    asm volatile("cp.async.commit_group;");

    for (int it = 0; it < nIt; it++) {
        const int s = it % 3;
        if (it + 1 < nIt) {
            if (ACONV) ldgA(it + 1);
            issueTile(it + 1, (it + 1) % 3);
            asm volatile("cp.async.commit_group;");
            asm volatile("cp.async.wait_group 1;");
        } else {
            asm volatile("cp.async.wait_group 0;");
        }
        __syncthreads();

        const uint32_t base = smBase + (uint32_t)(s * STAGE) * 2;
        const uint32_t aHiB = base, aLoB = base + ASZ * 2;
        const uint32_t bHiB = base + 2 * ASZ * 2, bLoB = bHiB + BSZ * 2;

#pragma unroll
        for (int ks = 0; ks < 2; ks++) {
            uint32_t ah[MF][4], al[MF][4], bh[NF][2], bl[NF][2];
#pragma unroll
            for (int mf = 0; mf < MF; mf++) {
                uint32_t off = (uint32_t)((wm * WTM + mf * 16 + (lid & 15)) * SKA
                                          + ks * 16 + (lid >> 4) * 8) * 2;
                ldsm4(aHiB + off, ah[mf][0], ah[mf][1], ah[mf][2], ah[mf][3]);
                ldsm4(aLoB + off, al[mf][0], al[mf][1], al[mf][2], al[mf][3]);
            }
            if (BTRANS) {
#pragma unroll
                for (int p = 0; p < NF / 2; p++) {
                    uint32_t off = (uint32_t)((ks * 16 + (lid & 15)) * SN
                                              + wn * WTN + p * 16 + (lid >> 4) * 8) * 2;
                    ldsm4t(bHiB + off, bh[2*p][0], bh[2*p][1], bh[2*p+1][0], bh[2*p+1][1]);
                    ldsm4t(bLoB + off, bl[2*p][0], bl[2*p][1], bl[2*p+1][0], bl[2*p+1][1]);
                }
            } else {
#pragma unroll
                for (int p = 0; p < NF / 2; p++) {
                    uint32_t off = (uint32_t)((wn * WTN + p * 16 + (lid & 7) + (lid >> 4) * 8) * SKA
                                              + ks * 16 + ((lid >> 3) & 1) * 8) * 2;
                    ldsm4(bHiB + off, bh[2*p][0], bh[2*p][1], bh[2*p+1][0], bh[2*p+1][1]);
                    ldsm4(bLoB + off, bl[2*p][0], bl[2*p][1], bl[2*p+1][0], bl[2*p+1][1]);
                }
            }
#pragma unroll
            for (int mf = 0; mf < MF; mf++)
#pragma unroll
                for (int nf = 0; nf < NF; nf++) {
                    mma16816(acc[mf][nf], ah[mf], bh[nf]);
                    mma16816(acc[mf][nf], ah[mf], bl[nf]);
                    mma16816(acc[mf][nf], al[mf], bh[nf]);
                }
        }
        if (ACONV && it + 1 < nIt) stsA((it + 1) % 3);
    }

    // ---- epilogue ----
    float* Cp = OSPLIT ? nullptr : (Cf + coff);
    __nv_bfloat16* ChP = OSPLIT ? (Chi + coff) : nullptr;
    __nv_bfloat16* ClP = OSPLIT ? (Clo + coff) : nullptr;
    const float* Ap2 = ADDF ? (Add + coff) : nullptr;
    const int rBase = row0 + wm * WTM + (lid >> 2);
    const int cBase = col0 + wn * WTN + (lid & 3) * 2;
#pragma unroll
    for (int mf = 0; mf < MF; mf++) {
#pragma unroll
        for (int half = 0; half < 2; half++) {
            const int gr = rBase + mf * 16 + half * 8;
            const float bm = BIAS_M ? bias[gr] : 0.f;
#pragma unroll
            for (int nf = 0; nf < NF; nf++) {
                const int gc = cBase + nf * 8;
                float v0 = acc[mf][nf][half * 2 + 0];
                float v1 = acc[mf][nf][half * 2 + 1];
                if (SCALEF) { v0 *= alpha; v1 *= alpha; }
                if (BIAS_M) { v0 += bm; v1 += bm; }
                if (BIAS_N) { v0 += bias[gc]; v1 += bias[gc + 1]; }
                if (GELUF) {
                    v0 = 0.5f * v0 * (1.0f + erff(v0 * 0.70710678118654752f));
                    v1 = 0.5f * v1 * (1.0f + erff(v1 * 0.70710678118654752f));
                }
                long off = (long)gr * ldc + gc;
                if (ADDF) { v0 += Ap2[off]; v1 += Ap2[off + 1]; }
                if (OSPLIT) {
                    __nv_bfloat16 h0, l0, h1, l1;
                    split1(v0, h0, l0); split1(v1, h1, l1);
                    __nv_bfloat16 hp[2] = {h0, h1}, lp[2] = {l0, l1};
                    *(uint32_t*)(ChP + off) = *(uint32_t*)hp;
                    *(uint32_t*)(ClP + off) = *(uint32_t*)lp;
                } else {
                    *(float2*)(Cp + off) = make_float2(v0, v1);
                }
            }
        }
    }
}

// =====================================================================================
// fp32 -> bf16 hi/lo convert (weights)
// =====================================================================================
__global__ void cvt_kernel(const float* __restrict__ s, __nv_bfloat16* __restrict__ hi,
                           __nv_bfloat16* __restrict__ lo, int n4)
{
    int i = blockIdx.x * 256 + threadIdx.x;
    if (i >= n4) return;
    float4 v = ((const float4*)s)[i];
    __nv_bfloat16 h[4], l[4];
    split1(v.x, h[0], l[0]); split1(v.y, h[1], l[1]);
    split1(v.z, h[2], l[2]); split1(v.w, h[3], l[3]);
    ((uint2*)hi)[i] = *(uint2*)h;
    ((uint2*)lo)[i] = *(uint2*)l;
}

__global__ void bias_gather(const float* a, const float* b, const float* c, float* o)
{
    const float* src[3] = {a, b, c};
    o[blockIdx.x * 1024 + threadIdx.x] = src[blockIdx.x][threadIdx.x];
}

// =====================================================================================
// channel LayerNorm; writes up to 3 affine outputs as bf16 hi/lo planes.
// =====================================================================================
__global__ void ln3_kernel(const float* __restrict__ x, int nOut,
    const float* __restrict__ w0, const float* __restrict__ b0,
    const float* __restrict__ w1, const float* __restrict__ b1,
    const float* __restrict__ w2, const float* __restrict__ b2,
    __nv_bfloat16* __restrict__ oHi, __nv_bfloat16* __restrict__ oLo)
{
    const int dx   = threadIdx.x & 31;
    const int lane = threadIdx.x >> 5;
    const int d    = blockIdx.x * 32 + dx;
    const long base = (long)blockIdx.y * CD + d;

    float s = 0.f, ss = 0.f;
    for (int c = lane; c < CC; c += 8) {
        float v = x[base + (long)c * DD];
        s += v; ss += v * v;
    }
    __shared__ float sS[8][33], sQ[8][33];
    sS[lane][dx] = s; sQ[lane][dx] = ss;
    __syncthreads();
    if (lane == 0) {
        float ts = 0.f, tq = 0.f;
        #pragma unroll
        for (int i = 0; i < 8; i++) { ts += sS[i][dx]; tq += sQ[i][dx]; }
        float mean = ts * (1.0f / CC);
        float var  = tq * (1.0f / CC) - mean * mean;
        sS[0][dx] = mean;
        sQ[0][dx] = rsqrtf(var + 1e-6f);
    }
    __syncthreads();
    const float mean = sS[0][dx];
    const float rstd = sQ[0][dx];
    const float* W[3] = {w0, w1, w2};
    const float* Bv[3] = {b0, b1, b2};
    for (int c = lane; c < CC; c += 8) {
        long idx = base + (long)c * DD;
        float xn = (x[idx] - mean) * rstd;
        for (int p = 0; p < nOut; p++) {
            float v = W[p][c] * xn + Bv[p][c];
            __nv_bfloat16 h, l;
            split1(v, h, l);
            oHi[(long)p * BCD + idx] = h;
            oLo[(long)p * BCD + idx] = l;
        }
    }
}

// =====================================================================================
// softmax-one over rows of 1024, in place (fp32 output buffer).
// =====================================================================================
__global__ void softmax_one_kernel(float* __restrict__ attn)
{
    float4* p = reinterpret_cast<float4*>(attn + (long)blockIdx.x * 1024);
    float4 f = p[threadIdx.x];

    float m = fmaxf(fmaxf(f.x, f.y), fmaxf(f.z, f.w));
    #pragma unroll
    for (int o = 16; o; o >>= 1) m = fmaxf(m, __shfl_xor_sync(0xffffffffu, m, o));
    __shared__ float smax[8], ssum[8];
    const int w = threadIdx.x >> 5, l = threadIdx.x & 31;
    if (l == 0) smax[w] = m;
    __syncthreads();
    if (threadIdx.x == 0) {
        float t = smax[0];
        #pragma unroll
        for (int i = 1; i < 8; i++) t = fmaxf(t, smax[i]);
        smax[0] = t;
    }
    __syncthreads();
    m = smax[0];

    float4 e;
    e.x = expf(f.x - m); e.y = expf(f.y - m);
    e.z = expf(f.z - m); e.w = expf(f.w - m);
    float s = e.x + e.y + e.z + e.w;
    #pragma unroll
    for (int o = 16; o; o >>= 1) s += __shfl_xor_sync(0xffffffffu, s, o);
    if (l == 0) ssum[w] = s;
    __syncthreads();
    if (threadIdx.x == 0) {
        float t = 0.f;
        #pragma unroll
        for (int i = 0; i < 8; i++) t += ssum[i];
        ssum[0] = t;
    }
    __syncthreads();
    const float inv = 1.0f / (1.0f + ssum[0]);
    e.x *= inv; e.y *= inv; e.z *= inv; e.w *= inv;
    p[threadIdx.x] = e;
}

// =====================================================================================
extern "C" void kernel_launch(void* const* d_in, const int* in_sizes, int n_in,
                              void* d_out, int out_size)
{
    const float* x1      = (const float*)d_in[0];
    const float* lnq_w   = (const float*)d_in[1];
    const float* lnq_b   = (const float*)d_in[2];
    const float* lnk_w   = (const float*)d_in[3];
    const float* lnk_b   = (const float*)d_in[4];
    const float* lnv_w   = (const float*)d_in[5];
    const float* lnv_b   = (const float*)d_in[6];
    const float* wq      = (const float*)d_in[7];
    const float* bq      = (const float*)d_in[8];
    const float* wk      = (const float*)d_in[9];
    const float* bk      = (const float*)d_in[10];
    const float* wv      = (const float*)d_in[11];
    const float* bv      = (const float*)d_in[12];
    const float* ffnln_w = (const float*)d_in[13];
    const float* ffnln_b = (const float*)d_in[14];
    const float* conv1_w = (const float*)d_in[15];
    const float* conv1_b = (const float*)d_in[16];
    const float* conv2_w = (const float*)d_in[17];
    const float* conv2_b = (const float*)d_in[18];

    __nv_bfloat16 *lnHi, *lnLo, *qkvHi, *qkvLo, *wHi, *wLo;
    __nv_bfloat16 *c1wHi, *c1wLo, *c2wHi, *c2wLo, *xlHi, *xlLo, *h1Hi, *h1Lo;
    float *xb, *bqkv;
    cudaGetSymbolAddress((void**)&lnHi,  g_ln_hi);   cudaGetSymbolAddress((void**)&lnLo,  g_ln_lo);
    cudaGetSymbolAddress((void**)&qkvHi, g_qkv_hi);  cudaGetSymbolAddress((void**)&qkvLo, g_qkv_lo);
    cudaGetSymbolAddress((void**)&wHi,   g_w_hi);    cudaGetSymbolAddress((void**)&wLo,   g_w_lo);
    cudaGetSymbolAddress((void**)&c1wHi, g_c1w_hi);  cudaGetSymbolAddress((void**)&c1wLo, g_c1w_lo);
    cudaGetSymbolAddress((void**)&c2wHi, g_c2w_hi);  cudaGetSymbolAddress((void**)&c2wLo, g_c2w_lo);
    cudaGetSymbolAddress((void**)&xlHi,  g_xl_hi);   cudaGetSymbolAddress((void**)&xlLo,  g_xl_lo);
    cudaGetSymbolAddress((void**)&h1Hi,  g_h1_hi);   cudaGetSymbolAddress((void**)&h1Lo,  g_h1_lo);
    cudaGetSymbolAddress((void**)&xb,    g_x);
    cudaGetSymbolAddress((void**)&bqkv,  g_bqkv);

    float* outx = (float*)d_out;            // (B,C,D)
    float* attn = outx + (long)BCD;         // (B,H,1024,1024)

    // kernel instantiations + smem sizes
    auto kQKV = tc2_gemm<128, false, false, false, true,  false, false, false, true >;
    auto kQK  = tc2_gemm<128, false, false, false, false, false, false, true,  false>;
    auto kPV  = tc2_gemm<64,  true,  true,  false, false, false, true,  false, false>;
    auto kC1  = tc2_gemm<128, true,  false, true,  false, true,  false, false, true >;
    auto kC2  = tc2_gemm<128, true,  false, true,  false, false, true,  false, false>;
    const int SM_BT128 = 3 * (2 * 128 * 40 + 2 * 128 * 40) * 2;  // 122880
    const int SM_TR128 = 3 * (2 * 128 * 40 + 2 * 32 * 136) * 2;  // 113664
    const int SM_TR64  = 3 * (2 * 128 * 40 + 2 * 32 * 72) * 2;   // 89088
    cudaFuncSetAttribute(kQKV, cudaFuncAttributeMaxDynamicSharedMemorySize, SM_BT128);
    cudaFuncSetAttribute(kQK,  cudaFuncAttributeMaxDynamicSharedMemorySize, SM_BT128);
    cudaFuncSetAttribute(kPV,  cudaFuncAttributeMaxDynamicSharedMemorySize, SM_TR64);
    cudaFuncSetAttribute(kC1,  cudaFuncAttributeMaxDynamicSharedMemorySize, SM_TR128);
    cudaFuncSetAttribute(kC2,  cudaFuncAttributeMaxDynamicSharedMemorySize, SM_TR128);

    // 0) pre-split weights + gather qkv biases
    cvt_kernel<<<CD / 4 / 256, 256>>>(wq, wHi,          wLo,          CD / 4);
    cvt_kernel<<<CD / 4 / 256, 256>>>(wk, wHi + CD,     wLo + CD,     CD / 4);
    cvt_kernel<<<CD / 4 / 256, 256>>>(wv, wHi + 2 * CD, wLo + 2 * CD, CD / 4);
    cvt_kernel<<<4 * CD / 4 / 256, 256>>>(conv1_w, c1wHi, c1wLo, 4 * CD / 4);
    cvt_kernel<<<4 * CD / 4 / 256, 256>>>(conv2_w, c2wHi, c2wLo, 4 * CD / 4);
    bias_gather<<<3, 1024>>>(bq, bk, bv, bqkv);

    // 1) QKV LayerNorms -> hi/lo planes
    dim3 lng(DD / 32, BB);
    ln3_kernel<<<lng, 256>>>(x1, 3, lnq_w, lnq_b, lnk_w, lnk_b, lnv_w, lnv_b, lnHi, lnLo);

    // 2) fused QKV linears (z = 0/1/2): y = ln_z @ W_z^T + b_z -> qkv plane z (hi/lo)
    dim3 gqkv(8, 32, 3);
    kQKV<<<gqkv, 256, SM_BT128>>>(lnHi, lnLo, BCD, 1024, wHi, wLo, 1, CD, 0, 1024,
                                  nullptr, qkvHi, qkvLo, 1, BCD, 0, 1024,
                                  nullptr, bqkv, 1024, 1.f, 4096, 1024, 1024);

    // 3) S = 0.125 * Q K^T per (b,h): contiguous (1024,64) head blocks
    dim3 gqk(8, 8, BB * HH);
    kQK<<<gqk, 256, SM_BT128>>>(qkvHi, qkvLo, 65536, 64,
                                qkvHi + BCD, qkvLo + BCD, 1, 65536, 0, 64,
                                attn, nullptr, nullptr, 1, 1048576, 0, 1024,
                                nullptr, nullptr, 0, 0.125f, 1024, 1024, 64);

    // 4) softmax-one in place
    softmax_one_kernel<<<BB * HH * 1024, 256>>>(attn);

    // 5) O = P V (A: fp32 probs converted in-kernel; B: v plane, N-contig trans path)
    //    scatter to x[b, i, h*64+e], fused residual add of x1
    dim3 gpv(1, 8, BB * HH);
    kPV<<<gpv, 256, SM_TR64>>>(attn, nullptr, 1048576, 1024,
                               qkvHi + 2 * (long)BCD, qkvLo + 2 * (long)BCD, 1, 65536, 0, 64,
                               xb, nullptr, nullptr, 16, CD, 64, 1024,
                               x1, nullptr, 0, 1.f, 1024, 64, 1024);

    // 6) FFN LayerNorm -> xl hi/lo
    ln3_kernel<<<lng, 256>>>(xb, 1, ffnln_w, ffnln_b, nullptr, nullptr, nullptr, nullptr,
                             xlHi, xlLo);

    // 7) conv1 (batched z=0..3): h1 = GELU(W1 @ xl_z + b1) -> h1 plane z (hi/lo)
    dim3 gc1(8, 32, BB);
    kC1<<<gc1, 256, SM_TR128>>>(c1wHi, c1wLo, 0, 1024, xlHi, xlLo, 1, CD, 0, 1024,
                                nullptr, h1Hi, h1Lo, 1, (long)4096 * 1024, 0, 1024,
                                nullptr, conv1_b, 0, 1.f, 4096, 1024, 1024);

    // 8) conv2 + residual: out = x + (W2 @ h1_z + b2)
    dim3 gc2(8, 8, BB);
    kC2<<<gc2, 256, SM_TR128>>>(c2wHi, c2wLo, 0, 4096, h1Hi, h1Lo, 1, (long)4096 * 1024, 0, 1024,
                                outx, nullptr, nullptr, 1, CD, 0, 1024,
                                xb, conv2_b, 0, 1.f, 1024, 1024, 4096);
}

// round 6
// speedup vs baseline: 2.6400x; 1.0252x over previous
#include <cuda_runtime.h>
#include <cuda_bf16.h>
#include <math.h>
#include <stdint.h>

#define BB   4
#define CC   1024
#define DD   1024
#define HH   16
#define CD   (CC*DD)          // 1048576
#define BCD  (BB*CD)          // 4194304
#define H1SZ (BB*4096*1024)   // 16777216

// ---------------- scratch (static __device__ arrays; no runtime alloc) ---------------
__device__ __nv_bfloat16 g_ln_hi[3*BCD],  g_ln_lo[3*BCD];    // lnq/lnk/lnv planes
__device__ __nv_bfloat16 g_qkv_hi[3*BCD], g_qkv_lo[3*BCD];   // q/k/v planes
__device__ __nv_bfloat16 g_w_hi[3*CD],    g_w_lo[3*CD];      // wq/wk/wv planes
__device__ __nv_bfloat16 g_c1w_hi[4*CD],  g_c1w_lo[4*CD];
__device__ __nv_bfloat16 g_c2w_hi[4*CD],  g_c2w_lo[4*CD];
__device__ __nv_bfloat16 g_xl_hi[BCD],    g_xl_lo[BCD];
__device__ __nv_bfloat16 g_h1_hi[H1SZ],   g_h1_lo[H1SZ];
__device__ float g_x[BCD];          // x1 + attention out (residual)
__device__ float g_bqkv[3*1024];    // gathered q/k/v biases

// =====================================================================================
// helpers
// =====================================================================================
__device__ __forceinline__ uint32_t smem_u32(const void* p) {
    uint32_t a;
    asm("{ .reg .u64 t; cvta.to.shared.u64 t, %1; cvt.u32.u64 %0, t; }" : "=r"(a) : "l"(p));
    return a;
}
__device__ __forceinline__ void cpa16(uint32_t s, const void* g) {
    asm volatile("cp.async.cg.shared.global [%0], [%1], 16;" :: "r"(s), "l"(g));
}
__device__ __forceinline__ void ldsm4(uint32_t addr, uint32_t& r0, uint32_t& r1,
                                      uint32_t& r2, uint32_t& r3) {
    asm volatile("ldmatrix.sync.aligned.m8n8.x4.shared.b16 {%0,%1,%2,%3}, [%4];"
                 : "=r"(r0), "=r"(r1), "=r"(r2), "=r"(r3) : "r"(addr));
}
__device__ __forceinline__ void ldsm4t(uint32_t addr, uint32_t& r0, uint32_t& r1,
                                       uint32_t& r2, uint32_t& r3) {
    asm volatile("ldmatrix.sync.aligned.m8n8.x4.trans.shared.b16 {%0,%1,%2,%3}, [%4];"
                 : "=r"(r0), "=r"(r1), "=r"(r2), "=r"(r3) : "r"(addr));
}
__device__ __forceinline__ void mma16816(float* c, const uint32_t* a, const uint32_t* b) {
    asm volatile(
        "mma.sync.aligned.m16n8k16.row.col.f32.bf16.bf16.f32 "
        "{%0,%1,%2,%3}, {%4,%5,%6,%7}, {%8,%9}, {%0,%1,%2,%3};"
        : "+f"(c[0]), "+f"(c[1]), "+f"(c[2]), "+f"(c[3])
        : "r"(a[0]), "r"(a[1]), "r"(a[2]), "r"(a[3]), "r"(b[0]), "r"(b[1]));
}
__device__ __forceinline__ void split1(float v, __nv_bfloat16& h, __nv_bfloat16& l) {
    h = __float2bfloat16(v);
    l = __float2bfloat16(v - __bfloat162float(h));
}

// =====================================================================================
// Generic tensor-core GEMM (pre-split bf16 hi/lo operands, 3-MMA fp32-class accuracy)
// =====================================================================================
template<int BN, bool BTRANS, bool ACONV, bool BIAS_M, bool BIAS_N,
         bool GELUF, bool ADDF, bool SCALEF, bool OSPLIT>
__global__ void __launch_bounds__(256, 1)
tc2_gemm(const void* Ahv, const __nv_bfloat16* Alo, long strideA, int lda,
         const __nv_bfloat16* Bhi, const __nv_bfloat16* Blo,
         int bDiv, long bHi, long bLo, int ldb,
         float* Cf, __nv_bfloat16* Chi, __nv_bfloat16* Clo,
         int cDiv, long cHi, long cLo, int ldc,
         const float* Add, const float* bias, int biasZ,
         float alpha, int M, int N, int K)
{
    constexpr int BK  = 32;
    constexpr int SKA = 40;
    constexpr int SN  = BN + 8;
    constexpr int ASZ = 128 * SKA;
    constexpr int BSZ = BTRANS ? (BK * SN) : (BN * SKA);
    constexpr int STAGE = 2 * ASZ + 2 * BSZ;
    constexpr int NW_M = (BN == 128) ? 2 : 4;
    constexpr int NW_N = 8 / NW_M;
    constexpr int WTM = 128 / NW_M;
    constexpr int WTN = BN / NW_N;
    constexpr int MF = WTM / 16;
    constexpr int NF = WTN / 8;

    extern __shared__ __nv_bfloat16 sm[];

    const int tid = threadIdx.x, wid = tid >> 5, lid = tid & 31;
    const int wm = wid / NW_N, wn = wid % NW_N;
    const int z = blockIdx.z;
    const int row0 = blockIdx.y * 128, col0 = blockIdx.x * BN;

    const __nv_bfloat16* Ahi = ACONV ? nullptr : ((const __nv_bfloat16*)Ahv + (long)z * strideA);
    const __nv_bfloat16* Alz = ACONV ? nullptr : (Alo + (long)z * strideA);
    const float* Af = ACONV ? ((const float*)Ahv + (long)z * strideA) : nullptr;
    Bhi += (long)(z / bDiv) * bHi + (long)(z % bDiv) * bLo;
    Blo += (long)(z / bDiv) * bHi + (long)(z % bDiv) * bLo;
    const long coff = (long)(z / cDiv) * cHi + (long)(z % cDiv) * cLo;
    if (BIAS_N || BIAS_M) bias += (long)z * biasZ;

    const uint32_t smBase = smem_u32(sm);
    const int nIt = K / BK;

    float acc[MF][NF][4];
#pragma unroll
    for (int i = 0; i < MF; i++)
#pragma unroll
        for (int j = 0; j < NF; j++)
#pragma unroll
            for (int r = 0; r < 4; r++) acc[i][j][r] = 0.f;

    float4 av[4];  // ACONV staging

    auto issueTile = [&](int it, int st) {
        const int k0 = it * BK;
        const uint32_t sbase = smBase + (uint32_t)(st * STAGE) * 2;
        if (!ACONV) {
#pragma unroll
            for (int pl = 0; pl < 2; pl++) {
                const __nv_bfloat16* Ag = pl ? Alz : Ahi;
                const uint32_t sd = sbase + (uint32_t)(pl * ASZ) * 2;
#pragma unroll
                for (int i = 0; i < 2; i++) {
                    int idx = tid + (i << 8);
                    int r = idx >> 2, c8 = (idx & 3) << 3;
                    cpa16(sd + (uint32_t)(r * SKA + c8) * 2,
                          Ag + (long)(row0 + r) * lda + k0 + c8);
                }
            }
        }
        if (BTRANS) {
            constexpr int CH = BK * BN / 8 / 256;
#pragma unroll
            for (int pl = 0; pl < 2; pl++) {
                const __nv_bfloat16* Bg = pl ? Blo : Bhi;
                const uint32_t sd = sbase + (uint32_t)(2 * ASZ + pl * BSZ) * 2;
#pragma unroll
                for (int i = 0; i < CH; i++) {
                    int idx = tid + (i << 8);
                    int k = idx / (BN / 8), c8 = (idx % (BN / 8)) << 3;
                    cpa16(sd + (uint32_t)(k * SN + c8) * 2,
                          Bg + (long)(k0 + k) * ldb + col0 + c8);
                }
            }
        } else {
#pragma unroll
            for (int pl = 0; pl < 2; pl++) {
                const __nv_bfloat16* Bg = pl ? Blo : Bhi;
                const uint32_t sd = sbase + (uint32_t)(2 * ASZ + pl * BSZ) * 2;
#pragma unroll
                for (int i = 0; i < BN / 64; i++) {
                    int idx = tid + (i << 8);
                    int r = idx >> 2, c8 = (idx & 3) << 3;
                    cpa16(sd + (uint32_t)(r * SKA + c8) * 2,
                          Bg + (long)(col0 + r) * ldb + k0 + c8);
                }
            }
        }
    };
    auto ldgA = [&](int it) {
        const int k0 = it * BK;
#pragma unroll
        for (int i = 0; i < 4; i++) {
            int idx = tid + (i << 8);
            int r = idx >> 3, c4 = (idx & 7) << 2;
            av[i] = *(const float4*)(Af + (long)(row0 + r) * lda + k0 + c4);
        }
    };
    auto stsA = [&](int st) {
        __nv_bfloat16* sAhi = sm + st * STAGE;
        __nv_bfloat16* sAlo = sAhi + ASZ;
#pragma unroll
        for (int i = 0; i < 4; i++) {
            int idx = tid + (i << 8);
            int r = idx >> 3, c4 = (idx & 7) << 2;
            __nv_bfloat16 h[4], l[4];
            split1(av[i].x, h[0], l[0]); split1(av[i].y, h[1], l[1]);
            split1(av[i].z, h[2], l[2]); split1(av[i].w, h[3], l[3]);
            *(uint2*)(sAhi + r * SKA + c4) = *(uint2*)h;
            *(uint2*)(sAlo + r * SKA + c4) = *(uint2*)l;
        }
    };

    if (ACONV) { ldgA(0); stsA(0); }
    issueTile(0, 0);
    asm volatile("cp.async.commit_group;");

    for (int it = 0; it < nIt; it++) {
        const int s = it % 3;
        if (it + 1 < nIt) {
            if (ACONV) ldgA(it + 1);
            issueTile(it + 1, (it + 1) % 3);
            asm volatile("cp.async.commit_group;");
            asm volatile("cp.async.wait_group 1;");
        } else {
            asm volatile("cp.async.wait_group 0;");
        }
        __syncthreads();

        const uint32_t base = smBase + (uint32_t)(s * STAGE) * 2;
        const uint32_t aHiB = base, aLoB = base + ASZ * 2;
        const uint32_t bHiB = base + 2 * ASZ * 2, bLoB = bHiB + BSZ * 2;

#pragma unroll
        for (int ks = 0; ks < 2; ks++) {
            uint32_t ah[MF][4], al[MF][4], bh[NF][2], bl[NF][2];
#pragma unroll
            for (int mf = 0; mf < MF; mf++) {
                uint32_t off = (uint32_t)((wm * WTM + mf * 16 + (lid & 15)) * SKA
                                          + ks * 16 + (lid >> 4) * 8) * 2;
                ldsm4(aHiB + off, ah[mf][0], ah[mf][1], ah[mf][2], ah[mf][3]);
                ldsm4(aLoB + off, al[mf][0], al[mf][1], al[mf][2], al[mf][3]);
            }
            if (BTRANS) {
#pragma unroll
                for (int p = 0; p < NF / 2; p++) {
                    uint32_t off = (uint32_t)((ks * 16 + (lid & 15)) * SN
                                              + wn * WTN + p * 16 + (lid >> 4) * 8) * 2;
                    ldsm4t(bHiB + off, bh[2*p][0], bh[2*p][1], bh[2*p+1][0], bh[2*p+1][1]);
                    ldsm4t(bLoB + off, bl[2*p][0], bl[2*p][1], bl[2*p+1][0], bl[2*p+1][1]);
                }
            } else {
#pragma unroll
                for (int p = 0; p < NF / 2; p++) {
                    uint32_t off = (uint32_t)((wn * WTN + p * 16 + (lid & 7) + (lid >> 4) * 8) * SKA
                                              + ks * 16 + ((lid >> 3) & 1) * 8) * 2;
                    ldsm4(bHiB + off, bh[2*p][0], bh[2*p][1], bh[2*p+1][0], bh[2*p+1][1]);
                    ldsm4(bLoB + off, bl[2*p][0], bl[2*p][1], bl[2*p+1][0], bl[2*p+1][1]);
                }
            }
#pragma unroll
            for (int mf = 0; mf < MF; mf++)
#pragma unroll
                for (int nf = 0; nf < NF; nf++) {
                    mma16816(acc[mf][nf], ah[mf], bh[nf]);
                    mma16816(acc[mf][nf], ah[mf], bl[nf]);
                    mma16816(acc[mf][nf], al[mf], bh[nf]);
                }
        }
        if (ACONV && it + 1 < nIt) stsA((it + 1) % 3);
    }

    // ---- epilogue ----
    float* Cp = OSPLIT ? nullptr : (Cf + coff);
    __nv_bfloat16* ChP = OSPLIT ? (Chi + coff) : nullptr;
    __nv_bfloat16* ClP = OSPLIT ? (Clo + coff) : nullptr;
    const float* Ap2 = ADDF ? (Add + coff) : nullptr;
    const int rBase = row0 + wm * WTM + (lid >> 2);
    const int cBase = col0 + wn * WTN + (lid & 3) * 2;
#pragma unroll
    for (int mf = 0; mf < MF; mf++) {
#pragma unroll
        for (int half = 0; half < 2; half++) {
            const int gr = rBase + mf * 16 + half * 8;
            const float bm = BIAS_M ? bias[gr] : 0.f;
#pragma unroll
            for (int nf = 0; nf < NF; nf++) {
                const int gc = cBase + nf * 8;
                float v0 = acc[mf][nf][half * 2 + 0];
                float v1 = acc[mf][nf][half * 2 + 1];
                if (SCALEF) { v0 *= alpha; v1 *= alpha; }
                if (BIAS_M) { v0 += bm; v1 += bm; }
                if (BIAS_N) { v0 += bias[gc]; v1 += bias[gc + 1]; }
                if (GELUF) {
                    v0 = 0.5f * v0 * (1.0f + erff(v0 * 0.70710678118654752f));
                    v1 = 0.5f * v1 * (1.0f + erff(v1 * 0.70710678118654752f));
                }
                long off = (long)gr * ldc + gc;
                if (ADDF) { v0 += Ap2[off]; v1 += Ap2[off + 1]; }
                if (OSPLIT) {
                    __nv_bfloat16 h0, l0, h1, l1;
                    split1(v0, h0, l0); split1(v1, h1, l1);
                    __nv_bfloat16 hp[2] = {h0, h1}, lp[2] = {l0, l1};
                    *(uint32_t*)(ChP + off) = *(uint32_t*)hp;
                    *(uint32_t*)(ClP + off) = *(uint32_t*)lp;
                } else {
                    *(float2*)(Cp + off) = make_float2(v0, v1);
                }
            }
        }
    }
}

// =====================================================================================
// Fused QK^T * 0.125 + softmax-one, writing normalized probs straight to attn out.
// grid (32, 64): x = 32-row block, y = z = b*16+h. 256 threads (8 warps).
// Per CTA: S rows [row0,row0+32) x all 1024 cols in registers (acc[2][8][2][4]).
// =====================================================================================
__global__ void __launch_bounds__(256, 1)
qk_softmax(const __nv_bfloat16* __restrict__ qHi, const __nv_bfloat16* __restrict__ qLo,
           const __nv_bfloat16* __restrict__ kHi, const __nv_bfloat16* __restrict__ kLo,
           float* __restrict__ attn)
{
    constexpr int SK = 72;                 // smem k-stride (64 + 8 pad)
    constexpr int QPL = 32 * SK;           // 2304 elems per Q plane
    constexpr int KPL = 128 * SK;          // 9216 elems per K plane
    extern __shared__ __nv_bfloat16 sm[];
    // layout: Q[2 planes] | K[2 stages][2 planes] | float red[2][32*9]
    float* redA = (float*)(sm + 2 * QPL + 4 * KPL);
    float* redB = redA + 32 * 9;

    const int tid = threadIdx.x, wid = tid >> 5, lid = tid & 31;
    const int z = blockIdx.y;
    const int row0 = blockIdx.x * 32;
    const __nv_bfloat16* Qh = qHi + (long)z * 65536;
    const __nv_bfloat16* Ql = qLo + (long)z * 65536;
    const __nv_bfloat16* Kh = kHi + (long)z * 65536;
    const __nv_bfloat16* Kl = kLo + (long)z * 65536;
    attn += (long)z * 1048576;

    const uint32_t smBase = smem_u32(sm);

    // ---- prologue: Q (once) + K chunk 0 ----
    {
        int r = tid >> 3, c8 = (tid & 7) << 3;
        cpa16(smBase + (uint32_t)(r * SK + c8) * 2,        Qh + (long)(row0 + r) * 64 + c8);
        cpa16(smBase + (uint32_t)(QPL + r * SK + c8) * 2,  Ql + (long)(row0 + r) * 64 + c8);
    }
    auto issueK = [&](int ch, int st) {
        const uint32_t sb = smBase + (uint32_t)(2 * QPL + st * 2 * KPL) * 2;
#pragma unroll
        for (int pl = 0; pl < 2; pl++) {
            const __nv_bfloat16* Kg = pl ? Kl : Kh;
            const uint32_t sd = sb + (uint32_t)(pl * KPL) * 2;
#pragma unroll
            for (int i = 0; i < 4; i++) {
                int idx = tid + (i << 8);
                int r = idx >> 3, c8 = (idx & 7) << 3;
                cpa16(sd + (uint32_t)(r * SK + c8) * 2,
                      Kg + (long)(ch * 128 + r) * 64 + c8);
            }
        }
    };
    issueK(0, 0);
    asm volatile("cp.async.commit_group;");

    float acc[2][8][2][4];
#pragma unroll
    for (int mf = 0; mf < 2; mf++)
#pragma unroll
        for (int ch = 0; ch < 8; ch++)
#pragma unroll
            for (int nf = 0; nf < 2; nf++)
#pragma unroll
                for (int r = 0; r < 4; r++) acc[mf][ch][nf][r] = 0.f;

    uint32_t aH[4][2][4], aL[4][2][4];    // [ks][mf][reg]

    for (int ch = 0; ch < 8; ch++) {
        asm volatile("cp.async.wait_group 0;");
        __syncthreads();
        if (ch + 1 < 8) {
            issueK(ch + 1, (ch + 1) & 1);
            asm volatile("cp.async.commit_group;");
        }
        if (ch == 0) {
            // preload Q fragments (reused by all chunks)
#pragma unroll
            for (int ks = 0; ks < 4; ks++)
#pragma unroll
                for (int mf = 0; mf < 2; mf++) {
                    uint32_t off = (uint32_t)((mf * 16 + (lid & 15)) * SK
                                              + ks * 16 + (lid >> 4) * 8) * 2;
                    ldsm4(smBase + off,           aH[ks][mf][0], aH[ks][mf][1],
                                                  aH[ks][mf][2], aH[ks][mf][3]);
                    ldsm4(smBase + QPL * 2 + off, aL[ks][mf][0], aL[ks][mf][1],
                                                  aL[ks][mf][2], aL[ks][mf][3]);
                }
        }
        const int st = ch & 1;
        const uint32_t kHiB = smBase + (uint32_t)(2 * QPL + st * 2 * KPL) * 2;
        const uint32_t kLoB = kHiB + (uint32_t)KPL * 2;
        const int wn = wid;
#pragma unroll
        for (int ks = 0; ks < 4; ks++) {
            uint32_t bh[2][2], bl[2][2];
            uint32_t off = (uint32_t)((wn * 16 + (lid & 7) + (lid >> 4) * 8) * SK
                                      + ks * 16 + ((lid >> 3) & 1) * 8) * 2;
            ldsm4(kHiB + off, bh[0][0], bh[0][1], bh[1][0], bh[1][1]);
            ldsm4(kLoB + off, bl[0][0], bl[0][1], bl[1][0], bl[1][1]);
#pragma unroll
            for (int mf = 0; mf < 2; mf++)
#pragma unroll
                for (int nf = 0; nf < 2; nf++) {
                    mma16816(acc[mf][ch][nf], aH[ks][mf], bh[nf]);
                    mma16816(acc[mf][ch][nf], aH[ks][mf], bl[nf]);
                    mma16816(acc[mf][ch][nf], aL[ks][mf], bh[nf]);
                }
        }
    }

    // ---- softmax-one across the full 1024-col rows ----
    const int rq = lid >> 2, cq = lid & 3;
    const int wn = wid;

    // scale
#pragma unroll
    for (int mf = 0; mf < 2; mf++)
#pragma unroll
        for (int ch = 0; ch < 8; ch++)
#pragma unroll
            for (int nf = 0; nf < 2; nf++)
#pragma unroll
                for (int r = 0; r < 4; r++) acc[mf][ch][nf][r] *= 0.125f;

    float mx[2][2];
#pragma unroll
    for (int mf = 0; mf < 2; mf++)
#pragma unroll
        for (int half = 0; half < 2; half++) {
            float m = -1e30f;
#pragma unroll
            for (int ch = 0; ch < 8; ch++)
#pragma unroll
                for (int nf = 0; nf < 2; nf++)
                    m = fmaxf(m, fmaxf(acc[mf][ch][nf][half*2], acc[mf][ch][nf][half*2+1]));
            m = fmaxf(m, __shfl_xor_sync(0xffffffffu, m, 1));
            m = fmaxf(m, __shfl_xor_sync(0xffffffffu, m, 2));
            mx[mf][half] = m;
        }
    if (cq == 0) {
#pragma unroll
        for (int mf = 0; mf < 2; mf++)
#pragma unroll
            for (int half = 0; half < 2; half++)
                redA[(mf * 16 + half * 8 + rq) * 9 + wid] = mx[mf][half];
    }
    __syncthreads();
#pragma unroll
    for (int mf = 0; mf < 2; mf++)
#pragma unroll
        for (int half = 0; half < 2; half++) {
            float m = -1e30f;
            const float* rr = redA + (mf * 16 + half * 8 + rq) * 9;
#pragma unroll
            for (int w = 0; w < 8; w++) m = fmaxf(m, rr[w]);
            mx[mf][half] = m;
        }

    float sum[2][2] = {{0.f, 0.f}, {0.f, 0.f}};
#pragma unroll
    for (int mf = 0; mf < 2; mf++)
#pragma unroll
        for (int half = 0; half < 2; half++) {
            const float m = mx[mf][half];
            float s = 0.f;
#pragma unroll
            for (int ch = 0; ch < 8; ch++)
#pragma unroll
                for (int nf = 0; nf < 2; nf++) {
                    float e0 = __expf(acc[mf][ch][nf][half*2]     - m);
                    float e1 = __expf(acc[mf][ch][nf][half*2 + 1] - m);
                    acc[mf][ch][nf][half*2]     = e0;
                    acc[mf][ch][nf][half*2 + 1] = e1;
                    s += e0 + e1;
                }
            s += __shfl_xor_sync(0xffffffffu, s, 1);
            s += __shfl_xor_sync(0xffffffffu, s, 2);
            sum[mf][half] = s;
        }
    if (cq == 0) {
#pragma unroll
        for (int mf = 0; mf < 2; mf++)
#pragma unroll
            for (int half = 0; half < 2; half++)
                redB[(mf * 16 + half * 8 + rq) * 9 + wid] = sum[mf][half];
    }
    __syncthreads();
#pragma unroll
    for (int mf = 0; mf < 2; mf++)
#pragma unroll
        for (int half = 0; half < 2; half++) {
            float s = 0.f;
            const float* rr = redB + (mf * 16 + half * 8 + rq) * 9;
#pragma unroll
            for (int w = 0; w < 8; w++) s += rr[w];
            sum[mf][half] = 1.0f / (1.0f + s);   // softmax-one denominator
        }

    // ---- write normalized probs ----
#pragma unroll
    for (int mf = 0; mf < 2; mf++)
#pragma unroll
        for (int half = 0; half < 2; half++) {
            const int gr = row0 + mf * 16 + half * 8 + rq;
            const float inv = sum[mf][half];
#pragma unroll
            for (int ch = 0; ch < 8; ch++)
#pragma unroll
                for (int nf = 0; nf < 2; nf++) {
                    const int gc = ch * 128 + wn * 16 + nf * 8 + cq * 2;
                    *(float2*)(attn + (long)gr * 1024 + gc) =
                        make_float2(acc[mf][ch][nf][half*2] * inv,
                                    acc[mf][ch][nf][half*2+1] * inv);
                }
        }
}

// =====================================================================================
// fp32 -> bf16 hi/lo convert (weights)
// =====================================================================================
__global__ void cvt_kernel(const float* __restrict__ s, __nv_bfloat16* __restrict__ hi,
                           __nv_bfloat16* __restrict__ lo, int n4)
{
    int i = blockIdx.x * 256 + threadIdx.x;
    if (i >= n4) return;
    float4 v = ((const float4*)s)[i];
    __nv_bfloat16 h[4], l[4];
    split1(v.x, h[0], l[0]); split1(v.y, h[1], l[1]);
    split1(v.z, h[2], l[2]); split1(v.w, h[3], l[3]);
    ((uint2*)hi)[i] = *(uint2*)h;
    ((uint2*)lo)[i] = *(uint2*)l;
}

__global__ void bias_gather(const float* a, const float* b, const float* c, float* o)
{
    const float* src[3] = {a, b, c};
    o[blockIdx.x * 1024 + threadIdx.x] = src[blockIdx.x][threadIdx.x];
}

// =====================================================================================
// channel LayerNorm; writes up to 3 affine outputs as bf16 hi/lo planes.
// =====================================================================================
__global__ void ln3_kernel(const float* __restrict__ x, int nOut,
    const float* __restrict__ w0, const float* __restrict__ b0,
    const float* __restrict__ w1, const float* __restrict__ b1,
    const float* __restrict__ w2, const float* __restrict__ b2,
    __nv_bfloat16* __restrict__ oHi, __nv_bfloat16* __restrict__ oLo)
{
    const int dx   = threadIdx.x & 31;
    const int lane = threadIdx.x >> 5;
    const int d    = blockIdx.x * 32 + dx;
    const long base = (long)blockIdx.y * CD + d;

    float s = 0.f, ss = 0.f;
    for (int c = lane; c < CC; c += 8) {
        float v = x[base + (long)c * DD];
        s += v; ss += v * v;
    }
    __shared__ float sS[8][33], sQ[8][33];
    sS[lane][dx] = s; sQ[lane][dx] = ss;
    __syncthreads();
    if (lane == 0) {
        float ts = 0.f, tq = 0.f;
        #pragma unroll
        for (int i = 0; i < 8; i++) { ts += sS[i][dx]; tq += sQ[i][dx]; }
        float mean = ts * (1.0f / CC);
        float var  = tq * (1.0f / CC) - mean * mean;
        sS[0][dx] = mean;
        sQ[0][dx] = rsqrtf(var + 1e-6f);
    }
    __syncthreads();
    const float mean = sS[0][dx];
    const float rstd = sQ[0][dx];
    const float* W[3] = {w0, w1, w2};
    const float* Bv[3] = {b0, b1, b2};
    for (int c = lane; c < CC; c += 8) {
        long idx = base + (long)c * DD;
        float xn = (x[idx] - mean) * rstd;
        for (int p = 0; p < nOut; p++) {
            float v = W[p][c] * xn + Bv[p][c];
            __nv_bfloat16 h, l;
            split1(v, h, l);
            oHi[(long)p * BCD + idx] = h;
            oLo[(long)p * BCD + idx] = l;
        }
    }
}

// =====================================================================================
extern "C" void kernel_launch(void* const* d_in, const int* in_sizes, int n_in,
                              void* d_out, int out_size)
{
    const float* x1      = (const float*)d_in[0];
    const float* lnq_w   = (const float*)d_in[1];
    const float* lnq_b   = (const float*)d_in[2];
    const float* lnk_w   = (const float*)d_in[3];
    const float* lnk_b   = (const float*)d_in[4];
    const float* lnv_w   = (const float*)d_in[5];
    const float* lnv_b   = (const float*)d_in[6];
    const float* wq      = (const float*)d_in[7];
    const float* bq      = (const float*)d_in[8];
    const float* wk      = (const float*)d_in[9];
    const float* bk      = (const float*)d_in[10];
    const float* wv      = (const float*)d_in[11];
    const float* bv      = (const float*)d_in[12];
    const float* ffnln_w = (const float*)d_in[13];
    const float* ffnln_b = (const float*)d_in[14];
    const float* conv1_w = (const float*)d_in[15];
    const float* conv1_b = (const float*)d_in[16];
    const float* conv2_w = (const float*)d_in[17];
    const float* conv2_b = (const float*)d_in[18];

    __nv_bfloat16 *lnHi, *lnLo, *qkvHi, *qkvLo, *wHi, *wLo;
    __nv_bfloat16 *c1wHi, *c1wLo, *c2wHi, *c2wLo, *xlHi, *xlLo, *h1Hi, *h1Lo;
    float *xb, *bqkv;
    cudaGetSymbolAddress((void**)&lnHi,  g_ln_hi);   cudaGetSymbolAddress((void**)&lnLo,  g_ln_lo);
    cudaGetSymbolAddress((void**)&qkvHi, g_qkv_hi);  cudaGetSymbolAddress((void**)&qkvLo, g_qkv_lo);
    cudaGetSymbolAddress((void**)&wHi,   g_w_hi);    cudaGetSymbolAddress((void**)&wLo,   g_w_lo);
    cudaGetSymbolAddress((void**)&c1wHi, g_c1w_hi);  cudaGetSymbolAddress((void**)&c1wLo, g_c1w_lo);
    cudaGetSymbolAddress((void**)&c2wHi, g_c2w_hi);  cudaGetSymbolAddress((void**)&c2wLo, g_c2w_lo);
    cudaGetSymbolAddress((void**)&xlHi,  g_xl_hi);   cudaGetSymbolAddress((void**)&xlLo,  g_xl_lo);
    cudaGetSymbolAddress((void**)&h1Hi,  g_h1_hi);   cudaGetSymbolAddress((void**)&h1Lo,  g_h1_lo);
    cudaGetSymbolAddress((void**)&xb,    g_x);
    cudaGetSymbolAddress((void**)&bqkv,  g_bqkv);

    float* outx = (float*)d_out;            // (B,C,D)
    float* attn = outx + (long)BCD;         // (B,H,1024,1024)

    auto kQKV = tc2_gemm<128, false, false, false, true,  false, false, false, true >;
    auto kPV  = tc2_gemm<64,  true,  true,  false, false, false, true,  false, false>;
    auto kC1  = tc2_gemm<128, true,  false, true,  false, true,  false, false, true >;
    auto kC2  = tc2_gemm<128, true,  false, true,  false, false, true,  false, false>;
    const int SM_BT128 = 3 * (2 * 128 * 40 + 2 * 128 * 40) * 2;  // 122880
    const int SM_TR128 = 3 * (2 * 128 * 40 + 2 * 32 * 136) * 2;  // 113664
    const int SM_TR64  = 3 * (2 * 128 * 40 + 2 * 32 * 72) * 2;   // 89088
    const int SM_QS = (2 * 32 * 72 + 4 * 128 * 72) * 2 + 2 * 32 * 9 * 4;  // 85248
    cudaFuncSetAttribute(kQKV, cudaFuncAttributeMaxDynamicSharedMemorySize, SM_BT128);
    cudaFuncSetAttribute(kPV,  cudaFuncAttributeMaxDynamicSharedMemorySize, SM_TR64);
    cudaFuncSetAttribute(kC1,  cudaFuncAttributeMaxDynamicSharedMemorySize, SM_TR128);
    cudaFuncSetAttribute(kC2,  cudaFuncAttributeMaxDynamicSharedMemorySize, SM_TR128);
    cudaFuncSetAttribute(qk_softmax, cudaFuncAttributeMaxDynamicSharedMemorySize, SM_QS);

    // 0) pre-split weights + gather qkv biases
    cvt_kernel<<<CD / 4 / 256, 256>>>(wq, wHi,          wLo,          CD / 4);
    cvt_kernel<<<CD / 4 / 256, 256>>>(wk, wHi + CD,     wLo + CD,     CD / 4);
    cvt_kernel<<<CD / 4 / 256, 256>>>(wv, wHi + 2 * CD, wLo + 2 * CD, CD / 4);
    cvt_kernel<<<4 * CD / 4 / 256, 256>>>(conv1_w, c1wHi, c1wLo, 4 * CD / 4);
    cvt_kernel<<<4 * CD / 4 / 256, 256>>>(conv2_w, c2wHi, c2wLo, 4 * CD / 4);
    bias_gather<<<3, 1024>>>(bq, bk, bv, bqkv);

    // 1) QKV LayerNorms -> hi/lo planes
    dim3 lng(DD / 32, BB);
    ln3_kernel<<<lng, 256>>>(x1, 3, lnq_w, lnq_b, lnk_w, lnk_b, lnv_w, lnv_b, lnHi, lnLo);

    // 2) fused QKV linears (z = 0/1/2)
    dim3 gqkv(8, 32, 3);
    kQKV<<<gqkv, 256, SM_BT128>>>(lnHi, lnLo, BCD, 1024, wHi, wLo, 1, CD, 0, 1024,
                                  nullptr, qkvHi, qkvLo, 1, BCD, 0, 1024,
                                  nullptr, bqkv, 1024, 1.f, 4096, 1024, 1024);

    // 3+4) fused S = softmax_one(0.125 * Q K^T) -> attn output
    dim3 gqs(32, BB * HH);
    qk_softmax<<<gqs, 256, SM_QS>>>(qkvHi, qkvLo, qkvHi + BCD, qkvLo + BCD, attn);

    // 5) O = P V (A: fp32 probs converted in-kernel; V: contiguous head block, trans path)
    dim3 gpv(1, 8, BB * HH);
    kPV<<<gpv, 256, SM_TR64>>>(attn, nullptr, 1048576, 1024,
                               qkvHi + 2 * (long)BCD, qkvLo + 2 * (long)BCD, 1, 65536, 0, 64,
                               xb, nullptr, nullptr, 16, CD, 64, 1024,
                               x1, nullptr, 0, 1.f, 1024, 64, 1024);

    // 6) FFN LayerNorm -> xl hi/lo
    ln3_kernel<<<lng, 256>>>(xb, 1, ffnln_w, ffnln_b, nullptr, nullptr, nullptr, nullptr,
                             xlHi, xlLo);

    // 7) conv1 (batched z=0..3): h1 = GELU(W1 @ xl_z + b1)
    dim3 gc1(8, 32, BB);
    kC1<<<gc1, 256, SM_TR128>>>(c1wHi, c1wLo, 0, 1024, xlHi, xlLo, 1, CD, 0, 1024,
                                nullptr, h1Hi, h1Lo, 1, (long)4096 * 1024, 0, 1024,
                                nullptr, conv1_b, 0, 1.f, 4096, 1024, 1024);

    // 8) conv2 + residual: out = x + (W2 @ h1_z + b2)
    dim3 gc2(8, 8, BB);
    kC2<<<gc2, 256, SM_TR128>>>(c2wHi, c2wLo, 0, 4096, h1Hi, h1Lo, 1, (long)4096 * 1024, 0, 1024,
                                outx, nullptr, nullptr, 1, CD, 0, 1024,
                                xb, conv2_b, 0, 1.f, 1024, 1024, 4096);
}